// round 14
// baseline (speedup 1.0000x reference)
#include <cuda_runtime.h>
#include <cuda_bf16.h>
#include <cstdint>

#define DDIM    512
#define MPTS    131072
#define BQ      64
#define STRIP_M 16
#define NSTRIPS (MPTS / STRIP_M)    // 8192
#define GRID    148
#define NTH     512
#define NWARPS  (GRID * NTH / 32)   // 2368

#define VSTRIDE 520                 // bf16 per n-row (bank-safe, proven)
#define VBYTES  (BQ * VSTRIDE * 2)  // 66560
#define S1_OFF   VBYTES
#define SA_OFF   (VBYTES + 256)
#define NRM_OFF  (VBYTES + 512)
#define WS_OFF   (VBYTES + 576)
#define SMEM_TOTAL (WS_OFF + DDIM * 4)

__device__ float g_part[GRID][BQ];

__device__ __forceinline__ float squashF(float x, float kk, float jj)
{
    float inner = x * (1.f - kk) * __fdividef(1.f, kk * (1.f - 2.f * fabsf(x)) + 1.f);
    float t = 2.f * inner - 1.f;
    return 0.5f + 0.5f * t * (1.f + jj) * __fdividef(1.f, -jj * (1.f - 2.f * fabsf(t)) + 1.f);
}

__device__ __forceinline__ void mma_bf16(float c[4], const uint32_t a[4],
                                         uint32_t b0, uint32_t b1)
{
    asm volatile(
        "mma.sync.aligned.m16n8k16.row.col.f32.bf16.bf16.f32 "
        "{%0,%1,%2,%3}, {%4,%5,%6,%7}, {%8,%9}, {%0,%1,%2,%3};\n"
        : "+f"(c[0]), "+f"(c[1]), "+f"(c[2]), "+f"(c[3])
        : "r"(a[0]), "r"(a[1]), "r"(a[2]), "r"(a[3]), "r"(b0), "r"(b1));
}

// 8 raw int32 loads for one k16 step; layout matches A-fragment q-mapping
__device__ __forceinline__ void ld8(int r[8], const int* __restrict__ p)
{
    r[0] = __ldcs(p);
    r[1] = __ldcs(p + MPTS);
    r[2] = __ldcs(p + 8);
    r[3] = __ldcs(p + MPTS + 8);
    r[4] = __ldcs(p + 8 * MPTS);
    r[5] = __ldcs(p + 9 * MPTS);
    r[6] = __ldcs(p + 8 * MPTS + 8);
    r[7] = __ldcs(p + 9 * MPTS + 8);
}

__device__ __forceinline__ void pack4(uint32_t a[4], const int r[8])
{
    a[0] = (uint32_t)r[0] * 0x3F80u + (uint32_t)r[1] * 0x3F800000u;
    a[1] = (uint32_t)r[2] * 0x3F80u + (uint32_t)r[3] * 0x3F800000u;
    a[2] = (uint32_t)r[4] * 0x3F80u + (uint32_t)r[5] * 0x3F800000u;
    a[3] = (uint32_t)r[6] * 0x3F80u + (uint32_t)r[7] * 0x3F800000u;
}

__global__ void __launch_bounds__(NTH, 1) knn_main(
    const int*   __restrict__ X1,   // [DDIM][BQ]
    const int*   __restrict__ X2,   // [DDIM][MPTS]
    const float* __restrict__ Y,    // [131072]
    const float* __restrict__ W,    // [DDIM]
    const float* __restrict__ kp,
    const float* __restrict__ jp)
{
    extern __shared__ char smem[];
    __nv_bfloat16* V_s = (__nv_bfloat16*)smem;
    float* s1_s  = (float*)(smem + S1_OFF);
    float* s_acc = (float*)(smem + SA_OFF);
    float* nrm_s = (float*)(smem + NRM_OFF);
    float* W_s   = (float*)(smem + WS_OFF);

    const int tid  = threadIdx.x;
    const int lane = tid & 31, warp = tid >> 5;
    const int g = lane >> 2, tig = lane & 3;

    // ---------------- prologue: V, s1, norm (proven) ----------------
    W_s[tid] = W[tid];
    if (tid < BQ) { s1_s[tid] = 0.f; s_acc[tid] = 0.f; }
    if (tid == 0) nrm_s[0] = 0.f;
    __syncthreads();
    {
        int b = tid & 63, part = tid >> 6;     // 8 parts of 64 d
        #pragma unroll 4
        for (int d = part; d < DDIM; d += 8) {
            float w = W_s[d];
            int x1 = X1[d * BQ + b];
            V_s[b * VSTRIDE + d] = __float2bfloat16(x1 ? -w : w);
        }
        float s = 0.f;
        #pragma unroll 4
        for (int d = part * 64; d < part * 64 + 64; d++)
            s += W_s[d] * (float)X1[d * BQ + b];
        atomicAdd(&s1_s[b], s);
        float a = fabsf(W_s[tid]);
        #pragma unroll
        for (int o = 16; o; o >>= 1) a += __shfl_down_sync(0xffffffffu, a, o);
        if (lane == 0) atomicAdd(nrm_s, a);
    }
    __syncthreads();

    const float inv_norm = __fdividef(1.f, nrm_s[0] + 1e-6f);
    const float kk = kp[0], jj = jp[0];

    // B ldmatrix lane addressing (proven)
    const int mi = lane >> 3, r8 = lane & 7;
    const int nt_a = mi >> 1, kh = mi & 1;
    const uint32_t v_base = (uint32_t)__cvta_generic_to_shared(V_s);
    uint32_t ldm[4];
    #pragma unroll
    for (int nb = 0; nb < 4; nb++)
        ldm[nb] = v_base + (uint32_t)(((nb * 16 + nt_a * 8 + r8) * VSTRIDE + kh * 8) * 2);

    const int gw = (int)blockIdx.x * (NTH / 32) + warp;   // global warp id

    float sc[16];
    #pragma unroll
    for (int i = 0; i < 16; i++) sc[i] = 0.f;

    int ra[8], rb[8];
    if (gw < NSTRIPS) {
        const int* pb0 = X2 + (size_t)(2 * tig) * MPTS + gw * STRIP_M + g;
        ld8(ra, pb0);
        ld8(rb, pb0 + (size_t)16 * MPTS);
    }

    // ---------------- mainloop: static grid-stride strips (proven R11) ----------------
    for (int strip = gw; strip < NSTRIPS; strip += NWARPS) {
        const int m0 = strip * STRIP_M;
        const int* pb = X2 + (size_t)(2 * tig) * MPTS + m0 + g;
        float acc[8][4];
        #pragma unroll
        for (int nf = 0; nf < 8; nf++)
            #pragma unroll
            for (int i = 0; i < 4; i++) acc[nf][i] = 0.f;

        #pragma unroll
        for (int s = 0; s < 32; s += 2) {
            uint32_t a[4];
            // ---- step s (from ra) ----
            pack4(a, ra);
            if (s + 2 < 32) ld8(ra, pb + (size_t)(s + 2) * 16 * MPTS);
            {
                uint32_t koff = (uint32_t)(s * 32);
                #pragma unroll
                for (int nb = 0; nb < 4; nb++) {
                    uint32_t b[4];
                    asm volatile(
                        "ldmatrix.sync.aligned.m8n8.x4.shared.b16 {%0,%1,%2,%3}, [%4];\n"
                        : "=r"(b[0]), "=r"(b[1]), "=r"(b[2]), "=r"(b[3])
                        : "r"(ldm[nb] + koff));
                    mma_bf16(acc[2 * nb],     a, b[0], b[1]);
                    mma_bf16(acc[2 * nb + 1], a, b[2], b[3]);
                }
            }
            // ---- step s+1 (from rb) ----
            pack4(a, rb);
            if (s + 3 < 32) ld8(rb, pb + (size_t)(s + 3) * 16 * MPTS);
            {
                uint32_t koff = (uint32_t)((s + 1) * 32);
                #pragma unroll
                for (int nb = 0; nb < 4; nb++) {
                    uint32_t b[4];
                    asm volatile(
                        "ldmatrix.sync.aligned.m8n8.x4.shared.b16 {%0,%1,%2,%3}, [%4];\n"
                        : "=r"(b[0]), "=r"(b[1]), "=r"(b[2]), "=r"(b[3])
                        : "r"(ldm[nb] + koff));
                    mma_bf16(acc[2 * nb],     a, b[0], b[1]);
                    mma_bf16(acc[2 * nb + 1], a, b[2], b[3]);
                }
            }
        }

        // ---- cross-strip prefetch: hide next strip's first loads under epilogue ----
        {
            int nstrip = strip + NWARPS;
            if (nstrip < NSTRIPS) {
                const int* pbn = X2 + (size_t)(2 * tig) * MPTS + nstrip * STRIP_M + g;
                ld8(ra, pbn);
                ld8(rb, pbn + (size_t)16 * MPTS);
            }
        }

        // ---- fused epilogue for this strip ----
        float y0 = __ldg(Y + m0 + g);
        float y1 = __ldg(Y + m0 + 8 + g);
        #pragma unroll
        for (int nf = 0; nf < 8; nf++) {
            int c0 = nf * 8 + 2 * tig;
            float s1a = s1_s[c0], s1b = s1_s[c0 + 1];
            float f00 = squashF(1.f - (s1a + acc[nf][0]) * inv_norm, kk, jj);
            float f01 = squashF(1.f - (s1b + acc[nf][1]) * inv_norm, kk, jj);
            float f10 = squashF(1.f - (s1a + acc[nf][2]) * inv_norm, kk, jj);
            float f11 = squashF(1.f - (s1b + acc[nf][3]) * inv_norm, kk, jj);
            sc[2 * nf]     += f00 * y0 + f10 * y1;
            sc[2 * nf + 1] += f01 * y0 + f11 * y1;
        }
    }

    // ---- reduce sc over the 8 g-lanes sharing each column set ----
    #pragma unroll
    for (int i = 0; i < 16; i++) {
        float v = sc[i];
        v += __shfl_down_sync(0xffffffffu, v, 16);
        v += __shfl_down_sync(0xffffffffu, v, 8);
        v += __shfl_down_sync(0xffffffffu, v, 4);
        if (lane < 4) {
            int col = (i >> 1) * 8 + 2 * lane + (i & 1);
            atomicAdd(&s_acc[col], v);
        }
    }
    __syncthreads();
    if (tid < BQ) g_part[blockIdx.x][tid] = s_acc[tid];
}

// -------------------- finalize: 1024 threads, 16-way partition, MLP-pipelined --------------------
__global__ void knn_final(const float* __restrict__ alpha,
                          const float* __restrict__ beta,
                          float* __restrict__ out)
{
    __shared__ float red[16][BQ];
    int b = threadIdx.x & 63, part = threadIdx.x >> 6;   // 1024 threads -> 16 parts
    float s = 0.f;
    for (int i = part; i < GRID; i += 16) s += g_part[i][b];
    red[part][b] = s;
    __syncthreads();
    if (threadIdx.x < BQ) {
        float t = 0.f;
        #pragma unroll
        for (int p = 0; p < 16; p++) t += red[p][threadIdx.x];
        out[threadIdx.x] = beta[0] * (t * (1.0f / (float)MPTS) + alpha[0]);
    }
}

// -------------------- launch --------------------
extern "C" void kernel_launch(void* const* d_in, const int* in_sizes, int n_in,
                              void* d_out, int out_size)
{
    const int*   X1    = (const int*)d_in[0];    // [512,64]
    const int*   X2    = (const int*)d_in[1];    // [512,131072]
    const float* Y     = (const float*)d_in[3];  // [131072]
    const float* W     = (const float*)d_in[4];  // [512]
    const float* alpha = (const float*)d_in[5];
    const float* beta  = (const float*)d_in[6];
    const float* kp    = (const float*)d_in[7];
    const float* jp    = (const float*)d_in[8];
    float* out = (float*)d_out;

    cudaFuncSetAttribute(knn_main, cudaFuncAttributeMaxDynamicSharedMemorySize, SMEM_TOTAL);

    knn_main<<<GRID, NTH, SMEM_TOTAL>>>(X1, X2, Y, W, kp, jp);
    knn_final<<<1, 1024>>>(alpha, beta, out);
}

// round 15
// speedup vs baseline: 1.0887x; 1.0887x over previous
#include <cuda_runtime.h>
#include <cuda_bf16.h>
#include <cstdint>

#define DDIM    512
#define MPTS    131072
#define BQ      64
#define STRIP_M 16
#define NSTRIPS (MPTS / STRIP_M)    // 8192
#define GRID    148
#define NTH     512
#define NWARPS  (GRID * NTH / 32)   // 2368

#define VSTRIDE 520                 // bf16 per n-row (bank-safe, proven)
#define VBYTES  (BQ * VSTRIDE * 2)  // 66560
#define S1_OFF   VBYTES
#define SA_OFF   (VBYTES + 256)
#define NRM_OFF  (VBYTES + 512)
#define WS_OFF   (VBYTES + 576)
#define SMEM_TOTAL (WS_OFF + DDIM * 4)

__device__ float g_acc[BQ];         // cross-CTA accumulators (reset by last CTA)
__device__ int   g_arrive = 0;      // CTA arrival counter    (reset by last CTA)

__device__ __forceinline__ float squashF(float x, float kk, float jj)
{
    float inner = x * (1.f - kk) * __fdividef(1.f, kk * (1.f - 2.f * fabsf(x)) + 1.f);
    float t = 2.f * inner - 1.f;
    return 0.5f + 0.5f * t * (1.f + jj) * __fdividef(1.f, -jj * (1.f - 2.f * fabsf(t)) + 1.f);
}

__device__ __forceinline__ void mma_bf16(float c[4], const uint32_t a[4],
                                         uint32_t b0, uint32_t b1)
{
    asm volatile(
        "mma.sync.aligned.m16n8k16.row.col.f32.bf16.bf16.f32 "
        "{%0,%1,%2,%3}, {%4,%5,%6,%7}, {%8,%9}, {%0,%1,%2,%3};\n"
        : "+f"(c[0]), "+f"(c[1]), "+f"(c[2]), "+f"(c[3])
        : "r"(a[0]), "r"(a[1]), "r"(a[2]), "r"(a[3]), "r"(b0), "r"(b1));
}

// 8 raw int32 loads for one k16 step; layout matches A-fragment q-mapping
__device__ __forceinline__ void ld8(int r[8], const int* __restrict__ p)
{
    r[0] = __ldcs(p);
    r[1] = __ldcs(p + MPTS);
    r[2] = __ldcs(p + 8);
    r[3] = __ldcs(p + MPTS + 8);
    r[4] = __ldcs(p + 8 * MPTS);
    r[5] = __ldcs(p + 9 * MPTS);
    r[6] = __ldcs(p + 8 * MPTS + 8);
    r[7] = __ldcs(p + 9 * MPTS + 8);
}

__device__ __forceinline__ void pack4(uint32_t a[4], const int r[8])
{
    a[0] = (uint32_t)r[0] * 0x3F80u + (uint32_t)r[1] * 0x3F800000u;
    a[1] = (uint32_t)r[2] * 0x3F80u + (uint32_t)r[3] * 0x3F800000u;
    a[2] = (uint32_t)r[4] * 0x3F80u + (uint32_t)r[5] * 0x3F800000u;
    a[3] = (uint32_t)r[6] * 0x3F80u + (uint32_t)r[7] * 0x3F800000u;
}

__global__ void __launch_bounds__(NTH, 1) knn_main(
    const int*   __restrict__ X1,   // [DDIM][BQ]
    const int*   __restrict__ X2,   // [DDIM][MPTS]
    const float* __restrict__ Y,    // [131072]
    const float* __restrict__ W,    // [DDIM]
    const float* __restrict__ alpha,
    const float* __restrict__ beta,
    const float* __restrict__ kp,
    const float* __restrict__ jp,
    float*       __restrict__ out)
{
    extern __shared__ char smem[];
    __nv_bfloat16* V_s = (__nv_bfloat16*)smem;
    float* s1_s  = (float*)(smem + S1_OFF);
    float* s_acc = (float*)(smem + SA_OFF);
    float* nrm_s = (float*)(smem + NRM_OFF);
    float* W_s   = (float*)(smem + WS_OFF);
    __shared__ int s_last;

    const int tid  = threadIdx.x;
    const int lane = tid & 31, warp = tid >> 5;
    const int g = lane >> 2, tig = lane & 3;

    // ---------------- prologue: V, s1, norm (proven R11) ----------------
    W_s[tid] = W[tid];
    if (tid < BQ) { s1_s[tid] = 0.f; s_acc[tid] = 0.f; }
    if (tid == 0) nrm_s[0] = 0.f;
    __syncthreads();
    {
        int b = tid & 63, part = tid >> 6;     // 8 parts of 64 d
        #pragma unroll 4
        for (int d = part; d < DDIM; d += 8) {
            float w = W_s[d];
            int x1 = X1[d * BQ + b];
            V_s[b * VSTRIDE + d] = __float2bfloat16(x1 ? -w : w);
        }
        float s = 0.f;
        #pragma unroll 4
        for (int d = part * 64; d < part * 64 + 64; d++)
            s += W_s[d] * (float)X1[d * BQ + b];
        atomicAdd(&s1_s[b], s);
        float a = fabsf(W_s[tid]);
        #pragma unroll
        for (int o = 16; o; o >>= 1) a += __shfl_down_sync(0xffffffffu, a, o);
        if (lane == 0) atomicAdd(nrm_s, a);
    }
    __syncthreads();

    const float inv_norm = __fdividef(1.f, nrm_s[0] + 1e-6f);
    const float kk = kp[0], jj = jp[0];

    // B ldmatrix lane addressing (proven)
    const int mi = lane >> 3, r8 = lane & 7;
    const int nt_a = mi >> 1, kh = mi & 1;
    const uint32_t v_base = (uint32_t)__cvta_generic_to_shared(V_s);
    uint32_t ldm[4];
    #pragma unroll
    for (int nb = 0; nb < 4; nb++)
        ldm[nb] = v_base + (uint32_t)(((nb * 16 + nt_a * 8 + r8) * VSTRIDE + kh * 8) * 2);

    const int gw = (int)blockIdx.x * (NTH / 32) + warp;   // global warp id

    float sc[16];
    #pragma unroll
    for (int i = 0; i < 16; i++) sc[i] = 0.f;

    // ---------------- mainloop: static grid-stride strips (proven R11, exact) ----------------
    for (int strip = gw; strip < NSTRIPS; strip += NWARPS) {
        const int m0 = strip * STRIP_M;
        float acc[8][4];
        #pragma unroll
        for (int nf = 0; nf < 8; nf++)
            #pragma unroll
            for (int i = 0; i < 4; i++) acc[nf][i] = 0.f;

        const int* pb = X2 + (size_t)(2 * tig) * MPTS + m0 + g;
        int ra[8], rb[8];
        ld8(ra, pb);
        ld8(rb, pb + (size_t)16 * MPTS);

        #pragma unroll
        for (int s = 0; s < 32; s += 2) {
            uint32_t a[4];
            // ---- step s (from ra) ----
            pack4(a, ra);
            if (s + 2 < 32) ld8(ra, pb + (size_t)(s + 2) * 16 * MPTS);
            {
                uint32_t koff = (uint32_t)(s * 32);
                #pragma unroll
                for (int nb = 0; nb < 4; nb++) {
                    uint32_t b[4];
                    asm volatile(
                        "ldmatrix.sync.aligned.m8n8.x4.shared.b16 {%0,%1,%2,%3}, [%4];\n"
                        : "=r"(b[0]), "=r"(b[1]), "=r"(b[2]), "=r"(b[3])
                        : "r"(ldm[nb] + koff));
                    mma_bf16(acc[2 * nb],     a, b[0], b[1]);
                    mma_bf16(acc[2 * nb + 1], a, b[2], b[3]);
                }
            }
            // ---- step s+1 (from rb) ----
            pack4(a, rb);
            if (s + 3 < 32) ld8(rb, pb + (size_t)(s + 3) * 16 * MPTS);
            {
                uint32_t koff = (uint32_t)((s + 1) * 32);
                #pragma unroll
                for (int nb = 0; nb < 4; nb++) {
                    uint32_t b[4];
                    asm volatile(
                        "ldmatrix.sync.aligned.m8n8.x4.shared.b16 {%0,%1,%2,%3}, [%4];\n"
                        : "=r"(b[0]), "=r"(b[1]), "=r"(b[2]), "=r"(b[3])
                        : "r"(ldm[nb] + koff));
                    mma_bf16(acc[2 * nb],     a, b[0], b[1]);
                    mma_bf16(acc[2 * nb + 1], a, b[2], b[3]);
                }
            }
        }

        // ---- fused epilogue for this strip ----
        float y0 = __ldg(Y + m0 + g);
        float y1 = __ldg(Y + m0 + 8 + g);
        #pragma unroll
        for (int nf = 0; nf < 8; nf++) {
            int c0 = nf * 8 + 2 * tig;
            float s1a = s1_s[c0], s1b = s1_s[c0 + 1];
            float f00 = squashF(1.f - (s1a + acc[nf][0]) * inv_norm, kk, jj);
            float f01 = squashF(1.f - (s1b + acc[nf][1]) * inv_norm, kk, jj);
            float f10 = squashF(1.f - (s1a + acc[nf][2]) * inv_norm, kk, jj);
            float f11 = squashF(1.f - (s1b + acc[nf][3]) * inv_norm, kk, jj);
            sc[2 * nf]     += f00 * y0 + f10 * y1;
            sc[2 * nf + 1] += f01 * y0 + f11 * y1;
        }
    }

    // ---- reduce sc over the 8 g-lanes sharing each column set ----
    #pragma unroll
    for (int i = 0; i < 16; i++) {
        float v = sc[i];
        v += __shfl_down_sync(0xffffffffu, v, 16);
        v += __shfl_down_sync(0xffffffffu, v, 8);
        v += __shfl_down_sync(0xffffffffu, v, 4);
        if (lane < 4) {
            int col = (i >> 1) * 8 + 2 * lane + (i & 1);
            atomicAdd(&s_acc[col], v);
        }
    }
    __syncthreads();

    // ---------------- light fused finalize ----------------
    // per-CTA: 64 spread-address global atomics (cheap, overlapped across CTAs)
    if (tid < BQ) atomicAdd(&g_acc[tid], s_acc[tid]);
    __threadfence();
    __syncthreads();
    if (tid == 0) {
        int v = atomicAdd(&g_arrive, 1);
        s_last = (v == GRID - 1);
    }
    __syncthreads();
    if (s_last) {
        if (tid < BQ) {
            float t = g_acc[tid];
            out[tid] = beta[0] * (t * (1.0f / (float)MPTS) + alpha[0]);
            g_acc[tid] = 0.f;          // reset for graph replay
        }
        __syncthreads();
        if (tid == 0) g_arrive = 0;    // reset for graph replay
    }
}

// -------------------- launch --------------------
extern "C" void kernel_launch(void* const* d_in, const int* in_sizes, int n_in,
                              void* d_out, int out_size)
{
    const int*   X1    = (const int*)d_in[0];    // [512,64]
    const int*   X2    = (const int*)d_in[1];    // [512,131072]
    const float* Y     = (const float*)d_in[3];  // [131072]
    const float* W     = (const float*)d_in[4];  // [512]
    const float* alpha = (const float*)d_in[5];
    const float* beta  = (const float*)d_in[6];
    const float* kp    = (const float*)d_in[7];
    const float* jp    = (const float*)d_in[8];
    float* out = (float*)d_out;

    cudaFuncSetAttribute(knn_main, cudaFuncAttributeMaxDynamicSharedMemorySize, SMEM_TOTAL);

    knn_main<<<GRID, NTH, SMEM_TOTAL>>>(X1, X2, Y, W, alpha, beta, kp, jp, out);
}